// round 15
// baseline (speedup 1.0000x reference)
#include <cuda_runtime.h>
#include <cuda_fp16.h>

typedef unsigned long long u64;
typedef unsigned int u32;

#define TSTEPS 128
#define NTH    512
#define MTILE  112

// =============== prepped weights (global scratch), fp16 ===============
// g_wh layout [l][side][kt(4)][gate(3)][q(4)][lane(32)][j(2)][reg(2)] u32
//   side0 = x-side weights (layer0: fused Wi0@We), side1 = w_hh
__device__ __align__(16) u32 g_wh[3 * 2 * 4 * 3 * 4 * 32 * 2 * 2];   // 36864 u32 = 147456 B
// combined biases per layer: [0:64)=bir+bhr(+bf_r) [64:128)=biz+bhz(+bf_z)
//                            [128:192)=bin(+bf_n)  [192:256)=bhn
__device__ __align__(16) float g_bias[3 * 256];

__device__ __forceinline__ u32 packh(float a, float b) {
    __half2 h2 = __floats2half2_rn(a, b);
    return *reinterpret_cast<u32*>(&h2);
}

__global__ void prep_kernel(const float* __restrict__ emb_w,
                            const float* __restrict__ emb_b,
                            const float* __restrict__ w_ih,
                            const float* __restrict__ w_hh,
                            const float* __restrict__ b_ih,
                            const float* __restrict__ b_hh)
{
    int i0 = blockIdx.x * blockDim.x + threadIdx.x;
    int st = gridDim.x * blockDim.x;
    for (int i = i0; i < 36864; i += st) {
        int reg  = i & 1;
        int j    = (i >> 1) & 1;
        int lane = (i >> 2) & 31;
        int qq   = (i >> 7) & 3;
        int gate = (i >> 9) % 3;
        int kt   = (i / 1536) % 4;
        int side = (i / 6144) % 2;
        int l    = i / 12288;
        int g = lane >> 2, tg = lane & 3;
        int n = (gate * 8 + qq * 2 + j) * 8 + g;        // column 0..191
        int k0 = kt * 16 + tg * 2 + reg * 8;
        float w0, w1;
        if (side == 1) {
            w0 = w_hh[(l * 192 + n) * 64 + k0];
            w1 = w_hh[(l * 192 + n) * 64 + k0 + 1];
        } else if (l > 0) {
            w0 = w_ih[(l * 192 + n) * 64 + k0];
            w1 = w_ih[(l * 192 + n) * 64 + k0 + 1];
        } else {
            // fused: Wf[n,k] = sum_e Wi0[n,e] * emb_w[e,k]
            float s0 = 0.f, s1 = 0.f;
            for (int e = 0; e < 64; e++) {
                float wi = w_ih[n * 64 + e];
                s0 += wi * emb_w[e * 64 + k0];
                s1 += wi * emb_w[e * 64 + k0 + 1];
            }
            w0 = s0; w1 = s1;
        }
        g_wh[i] = packh(w0, w1);
    }
    for (int i = i0; i < 3 * 64; i += st) {
        int l = i >> 6, c = i & 63;
        float bfr = 0.f, bfz = 0.f, bfn = 0.f;
        if (l == 0) {
            for (int e = 0; e < 64; e++) {
                float be = emb_b[e];
                bfr += be * w_ih[c * 64 + e];
                bfz += be * w_ih[(64 + c) * 64 + e];
                bfn += be * w_ih[(128 + c) * 64 + e];
            }
        }
        g_bias[l * 256 + c]       = b_ih[l * 192 + c]      + b_hh[l * 192 + c]      + bfr;
        g_bias[l * 256 + 64 + c]  = b_ih[l * 192 + 64 + c] + b_hh[l * 192 + 64 + c] + bfz;
        g_bias[l * 256 + 128 + c] = b_ih[l * 192 + 128 + c] + bfn;
        g_bias[l * 256 + 192 + c] = b_hh[l * 192 + 128 + c];
    }
}

// =============== device helpers ===============
__device__ __forceinline__ u32 smem_u32(const void* p) {
    u32 a;
    asm("{ .reg .u64 t; cvta.to.shared.u64 t, %1; cvt.u32.u64 %0, t; }" : "=r"(a) : "l"(p));
    return a;
}
__device__ __forceinline__ void mma16816h(float* d, const u32* a, u32 b0, u32 b1) {
    asm volatile(
        "mma.sync.aligned.m16n8k16.row.col.f32.f16.f16.f32 "
        "{%0,%1,%2,%3},{%4,%5,%6,%7},{%8,%9},{%0,%1,%2,%3};"
        : "+f"(d[0]), "+f"(d[1]), "+f"(d[2]), "+f"(d[3])
        : "r"(a[0]), "r"(a[1]), "r"(a[2]), "r"(a[3]), "r"(b0), "r"(b1));
}
__device__ __forceinline__ void lds128(u32* r, u32 a) {
    asm volatile("ld.shared.v4.u32 {%0,%1,%2,%3},[%4];"
                 : "=r"(r[0]), "=r"(r[1]), "=r"(r[2]), "=r"(r[3]) : "r"(a));
}
__device__ __forceinline__ void lds64(u32& x, u32& y, u32 a) {
    asm volatile("ld.shared.v2.u32 {%0,%1},[%2];" : "=r"(x), "=r"(y) : "r"(a));
}
__device__ __forceinline__ void sts64(u32 a, u32 x, u32 y) {
    asm volatile("st.shared.v2.u32 [%0],{%1,%2};" :: "r"(a), "r"(x), "r"(y));
}
__device__ __forceinline__ void cpasync16(u32 s, const void* g) {
    asm volatile("cp.async.ca.shared.global [%0],[%1],16;" :: "r"(s), "l"(g));
}
__device__ __forceinline__ void cpcommit() { asm volatile("cp.async.commit_group;"); }
__device__ __forceinline__ void cpwaitall() { asm volatile("cp.async.wait_group 0;"); }
__device__ __forceinline__ void named_bar(int id) {
    asm volatile("bar.sync %0, 128;" :: "r"(id) : "memory");
}
__device__ __forceinline__ float sigmf(float x) { return __fdividef(1.f, 1.f + __expf(-x)); }
__device__ __forceinline__ float tanhfast(float x) { return 1.f - __fdividef(2.f, __expf(2.f * x) + 1.f); }

// SMEM layout (bytes), 112-row CTA:
//   fp16 states S0,S1,S2 (h0,h1,h2) at s*14336          = 43008
//   output partials at SO_P (7mt x 4q x 16 x 2 f32)     = 3584
//   weights (single resident copy) at SO_W              = 147456
#define SO_P   43008
#define SO_W   46592
#define SMEMSZ (SO_W + 147456)   /* 194048 */

extern "C" __global__ void __launch_bounds__(NTH, 1)
gru_mma_kernel(const float* __restrict__ enc,
               const float* __restrict__ out_w,
               const float* __restrict__ out_b,
               float* __restrict__ out)
{
    extern __shared__ char smc[];
    const u32 sb   = smem_u32(smc);
    const int tid  = threadIdx.x;
    const int lane = tid & 31;
    const int warp = tid >> 5;            // 16 warps
    const int p    = warp >> 2;           // 4 pair-groups: p<3 own mt{2p,2p+1}, p=3 owns mt6
    const int q    = warp & 3;            // column quarter (16 cols of 64)
    const int g    = lane >> 2;
    const int tg   = lane & 3;
    const int row0 = blockIdx.x * MTILE;
    const int barid = 1 + p;              // per-p named barrier (128 threads)
    const bool hasB = (p < 3);
    const int mtA = 2 * p;
    const int mtB = hasB ? (2 * p + 1) : (2 * p);

    // x-source / h-source state index per layer (x of layer0 = h2 = S[2])
    const int xs[3] = {2, 0, 1};
    const int hs[3] = {0, 1, 2};

    // ---- load ALL weights into SMEM once (resident for the whole run) ----
    for (int o = tid * 16; o < 147456; o += NTH * 16)
        cpasync16(sb + SO_W + o, (const char*)g_wh + o);
    cpcommit();

    // ---- init fp16 states from enc (guarded rows) ----
    for (int i = tid; i < MTILE * 32; i += NTH) {
        int m = i >> 5, kp = i & 31;
        int k = kp * 2;
        int rr = row0 + m; if (rr > 16383) rr = 16383;
        float v0 = enc[(size_t)rr * 64 + k];
        float v1 = enc[(size_t)rr * 64 + k + 1];
        u32 h16 = packh(v0, v1);
        int kt = k >> 4, kin = k & 15;
        int gg = m & 15;
        int reg = ((kin >= 8) ? 2 : 0) + ((gg >= 8) ? 1 : 0);
        int ln = (gg & 7) * 4 + ((kin & 7) >> 1);
        u32 off = (u32)((m >> 4) * 2048 + kt * 512 + ln * 16 + reg * 4);
        #pragma unroll
        for (int s = 0; s < 3; s++)
            *(u32*)(smc + s * 14336 + off) = h16;
    }
    cpwaitall();
    __syncthreads();   // the ONLY CTA-wide barrier; hot loop uses per-p bars

    const u32 aoffA = (u32)(mtA * 2048 + lane * 16);
    const u32 aoffB = (u32)(mtB * 2048 + lane * 16);
    float* sp = (float*)(smc + SO_P);

    #pragma unroll 1
    for (int t = 0; t < TSTEPS; t++) {

        #pragma unroll 1
        for (int l = 0; l < 3; l++) {

            // acc[mt][gatekind][j][4]
            float aR[2][2][4], aZ[2][2][4], aN[2][2][4], aM[2][2][4];
            #pragma unroll
            for (int m = 0; m < 2; m++)
                #pragma unroll
                for (int j = 0; j < 2; j++)
                    #pragma unroll
                    for (int e = 0; e < 4; e++) {
                        aR[m][j][e]=0.f; aZ[m][j][e]=0.f;
                        aN[m][j][e]=0.f; aM[m][j][e]=0.f;
                    }

            {
                #pragma unroll
                for (int side = 0; side < 2; side++) {    // 0 = x-side, 1 = h-side
                    const int stA = (side == 0) ? xs[l] : hs[l];
                    const u32 abA = sb + (u32)(stA * 14336) + aoffA;
                    const u32 abB = sb + (u32)(stA * 14336) + aoffB;
                    const u32 wside = sb + SO_W + (u32)(l * 49152 + side * 24576);
                    #pragma unroll 1
                    for (int kt = 0; kt < 4; kt++) {
                        u32 ahA[4], ahB[4];
                        lds128(ahA, abA + (u32)(kt * 512));
                        if (hasB) lds128(ahB, abB + (u32)(kt * 512));
                        #pragma unroll
                        for (int gate = 0; gate < 3; gate++) {
                            u32 b4[4];
                            lds128(b4, wside + (u32)(((kt * 12 + gate * 4 + q) * 32 + lane) * 16));
                            {
                                float (*acc)[4] = (gate == 0) ? aR[0] :
                                                  (gate == 1) ? aZ[0] :
                                                  ((side == 0) ? aN[0] : aM[0]);
                                mma16816h(acc[0], ahA, b4[0], b4[1]);
                                mma16816h(acc[1], ahA, b4[2], b4[3]);
                            }
                            if (hasB) {
                                float (*acc)[4] = (gate == 0) ? aR[1] :
                                                  (gate == 1) ? aZ[1] :
                                                  ((side == 0) ? aN[1] : aM[1]);
                                mma16816h(acc[0], ahB, b4[0], b4[1]);
                                mma16816h(acc[1], ahB, b4[2], b4[3]);
                            }
                        }
                    }
                }
            }
            // peers' A-loads of h_l must finish before epilogue rewrites it
            named_bar(barid);

            // ---- layer epilogue per owned mtile ----
            const float* gb = g_bias + l * 256;
            #pragma unroll
            for (int mx = 0; mx < 2; mx++) {
                if (mx == 1 && !hasB) break;
                const int mtx = 2 * p + mx;
                const u32 hbase16 = sb + (u32)(hs[l] * 14336 + mtx * 2048) + (u32)(lane * 16);
                float oA0 = 0.f, oA1 = 0.f, oB0 = 0.f, oB1 = 0.f;
                #pragma unroll
                for (int j = 0; j < 2; j++) {
                    int ntc = q * 2 + j;
                    int c0 = ntc * 8 + 2 * tg;
                    float br0 = __ldg(gb + c0),        br1 = __ldg(gb + c0 + 1);
                    float bz0 = __ldg(gb + 64 + c0),   bz1 = __ldg(gb + 64 + c0 + 1);
                    float bn0 = __ldg(gb + 128 + c0),  bn1 = __ldg(gb + 128 + c0 + 1);
                    float bm0 = __ldg(gb + 192 + c0),  bm1 = __ldg(gb + 192 + c0 + 1);
                    u32 ad16 = hbase16 + (u32)((ntc >> 1) * 512 + (ntc & 1) * 8);
                    u32 hh0, hh1;
                    lds64(hh0, hh1, ad16);
                    float2 hoA = __half22float2(*reinterpret_cast<__half2*>(&hh0));
                    float2 hoB = __half22float2(*reinterpret_cast<__half2*>(&hh1));

                    float r, z, n;
                    r = sigmf(aR[mx][j][0] + br0); z = sigmf(aZ[mx][j][0] + bz0);
                    n = tanhfast(aN[mx][j][0] + bn0 + r * (aM[mx][j][0] + bm0));
                    float h00 = n + z * (hoA.x - n);
                    r = sigmf(aR[mx][j][1] + br1); z = sigmf(aZ[mx][j][1] + bz1);
                    n = tanhfast(aN[mx][j][1] + bn1 + r * (aM[mx][j][1] + bm1));
                    float h01 = n + z * (hoA.y - n);
                    r = sigmf(aR[mx][j][2] + br0); z = sigmf(aZ[mx][j][2] + bz0);
                    n = tanhfast(aN[mx][j][2] + bn0 + r * (aM[mx][j][2] + bm0));
                    float h10 = n + z * (hoB.x - n);
                    r = sigmf(aR[mx][j][3] + br1); z = sigmf(aZ[mx][j][3] + bz1);
                    n = tanhfast(aN[mx][j][3] + bn1 + r * (aM[mx][j][3] + bm1));
                    float h11 = n + z * (hoB.y - n);

                    sts64(ad16, packh(h00, h01), packh(h10, h11));

                    if (l == 2) {
                        float w00 = __ldg(out_w + c0),      w01 = __ldg(out_w + c0 + 1);
                        float w10 = __ldg(out_w + 64 + c0), w11 = __ldg(out_w + 64 + c0 + 1);
                        oA0 += h00 * w00 + h01 * w01;
                        oA1 += h00 * w10 + h01 * w11;
                        oB0 += h10 * w00 + h11 * w01;
                        oB1 += h10 * w10 + h11 * w11;
                    }
                }
                if (l == 2) {
                    #pragma unroll
                    for (int m = 1; m <= 2; m <<= 1) {
                        oA0 += __shfl_xor_sync(0xffffffffu, oA0, m);
                        oA1 += __shfl_xor_sync(0xffffffffu, oA1, m);
                        oB0 += __shfl_xor_sync(0xffffffffu, oB0, m);
                        oB1 += __shfl_xor_sync(0xffffffffu, oB1, m);
                    }
                    if (tg == 0) {
                        int base = ((mtx * 4 + q) * 16 + g) * 2;
                        sp[base]     = oA0;
                        sp[base + 1] = oA1;
                        int base2 = ((mtx * 4 + q) * 16 + g + 8) * 2;
                        sp[base2]     = oB0;
                        sp[base2 + 1] = oB1;
                    }
                }
            }

            // epilogue state writes (and partials) visible to p-group peers
            named_bar(barid);

            if (l == 2 && q == 0) {
                #pragma unroll
                for (int mx = 0; mx < 2; mx++) {
                    if (mx == 1 && !hasB) break;
                    const int mtx = 2 * p + mx;
                    int row = lane >> 1, j = lane & 1;
                    float v = sp[((mtx * 4 + 0) * 16 + row) * 2 + j] +
                              sp[((mtx * 4 + 1) * 16 + row) * 2 + j] +
                              sp[((mtx * 4 + 2) * 16 + row) * 2 + j] +
                              sp[((mtx * 4 + 3) * 16 + row) * 2 + j] + __ldg(out_b + j);
                    int grow = row0 + mtx * 16 + row;
                    if (grow < 16384)
                        out[(size_t)grow * (TSTEPS * 2) + t * 2 + j] = v;
                }
            }
        }
    }
}

extern "C" void kernel_launch(void* const* d_in, const int* in_sizes, int n_in,
                              void* d_out, int out_size)
{
    const float* enc   = (const float*)d_in[0];
    const float* emb_w = (const float*)d_in[1];
    const float* emb_b = (const float*)d_in[2];
    const float* w_ih  = (const float*)d_in[3];
    const float* w_hh  = (const float*)d_in[4];
    const float* b_ih  = (const float*)d_in[5];
    const float* b_hh  = (const float*)d_in[6];
    const float* out_w = (const float*)d_in[7];
    const float* out_b = (const float*)d_in[8];

    cudaFuncSetAttribute(gru_mma_kernel,
                         cudaFuncAttributeMaxDynamicSharedMemorySize, SMEMSZ);

    prep_kernel<<<96, 256>>>(emb_w, emb_b, w_ih, w_hh, b_ih, b_hh);
    gru_mma_kernel<<<152, NTH, SMEMSZ>>>(enc, out_w, out_b, (float*)d_out);
}

// round 16
// speedup vs baseline: 1.1655x; 1.1655x over previous
#include <cuda_runtime.h>
#include <cuda_fp16.h>

typedef unsigned long long u64;
typedef unsigned int u32;

#define TSTEPS 128
#define NTH    896
#define MTILE  112

// =============== prepped weights (global scratch), fp16 ===============
// g_wh layout [l][side][kt(4)][gate(3)][q(4)][lane(32)][j(2)][reg(2)] u32
//   side0 = x-side weights (layer0: fused Wi0@We), side1 = w_hh
__device__ __align__(16) u32 g_wh[3 * 2 * 4 * 3 * 4 * 32 * 2 * 2];   // 36864 u32 = 147456 B
// combined biases per layer: [0:64)=bir+bhr(+bf_r) [64:128)=biz+bhz(+bf_z)
//                            [128:192)=bin(+bf_n)  [192:256)=bhn
__device__ __align__(16) float g_bias[3 * 256];

__device__ __forceinline__ u32 packh(float a, float b) {
    __half2 h2 = __floats2half2_rn(a, b);
    return *reinterpret_cast<u32*>(&h2);
}

__global__ void prep_kernel(const float* __restrict__ emb_w,
                            const float* __restrict__ emb_b,
                            const float* __restrict__ w_ih,
                            const float* __restrict__ w_hh,
                            const float* __restrict__ b_ih,
                            const float* __restrict__ b_hh)
{
    int i0 = blockIdx.x * blockDim.x + threadIdx.x;
    int st = gridDim.x * blockDim.x;
    for (int i = i0; i < 36864; i += st) {
        int reg  = i & 1;
        int j    = (i >> 1) & 1;
        int lane = (i >> 2) & 31;
        int qq   = (i >> 7) & 3;
        int gate = (i >> 9) % 3;
        int kt   = (i / 1536) % 4;
        int side = (i / 6144) % 2;
        int l    = i / 12288;
        int g = lane >> 2, tg = lane & 3;
        int n = (gate * 8 + qq * 2 + j) * 8 + g;        // column 0..191
        int k0 = kt * 16 + tg * 2 + reg * 8;
        float w0, w1;
        if (side == 1) {
            w0 = w_hh[(l * 192 + n) * 64 + k0];
            w1 = w_hh[(l * 192 + n) * 64 + k0 + 1];
        } else if (l > 0) {
            w0 = w_ih[(l * 192 + n) * 64 + k0];
            w1 = w_ih[(l * 192 + n) * 64 + k0 + 1];
        } else {
            // fused: Wf[n,k] = sum_e Wi0[n,e] * emb_w[e,k]
            float s0 = 0.f, s1 = 0.f;
            for (int e = 0; e < 64; e++) {
                float wi = w_ih[n * 64 + e];
                s0 += wi * emb_w[e * 64 + k0];
                s1 += wi * emb_w[e * 64 + k0 + 1];
            }
            w0 = s0; w1 = s1;
        }
        g_wh[i] = packh(w0, w1);
    }
    for (int i = i0; i < 3 * 64; i += st) {
        int l = i >> 6, c = i & 63;
        float bfr = 0.f, bfz = 0.f, bfn = 0.f;
        if (l == 0) {
            for (int e = 0; e < 64; e++) {
                float be = emb_b[e];
                bfr += be * w_ih[c * 64 + e];
                bfz += be * w_ih[(64 + c) * 64 + e];
                bfn += be * w_ih[(128 + c) * 64 + e];
            }
        }
        g_bias[l * 256 + c]       = b_ih[l * 192 + c]      + b_hh[l * 192 + c]      + bfr;
        g_bias[l * 256 + 64 + c]  = b_ih[l * 192 + 64 + c] + b_hh[l * 192 + 64 + c] + bfz;
        g_bias[l * 256 + 128 + c] = b_ih[l * 192 + 128 + c] + bfn;
        g_bias[l * 256 + 192 + c] = b_hh[l * 192 + 128 + c];
    }
}

// =============== device helpers ===============
__device__ __forceinline__ u32 smem_u32(const void* p) {
    u32 a;
    asm("{ .reg .u64 t; cvta.to.shared.u64 t, %1; cvt.u32.u64 %0, t; }" : "=r"(a) : "l"(p));
    return a;
}
__device__ __forceinline__ void mma16816h(float* d, const u32* a, u32 b0, u32 b1) {
    asm volatile(
        "mma.sync.aligned.m16n8k16.row.col.f32.f16.f16.f32 "
        "{%0,%1,%2,%3},{%4,%5,%6,%7},{%8,%9},{%0,%1,%2,%3};"
        : "+f"(d[0]), "+f"(d[1]), "+f"(d[2]), "+f"(d[3])
        : "r"(a[0]), "r"(a[1]), "r"(a[2]), "r"(a[3]), "r"(b0), "r"(b1));
}
__device__ __forceinline__ void lds128(u32* r, u32 a) {
    asm volatile("ld.shared.v4.u32 {%0,%1,%2,%3},[%4];"
                 : "=r"(r[0]), "=r"(r[1]), "=r"(r[2]), "=r"(r[3]) : "r"(a));
}
__device__ __forceinline__ void lds64(u32& x, u32& y, u32 a) {
    asm volatile("ld.shared.v2.u32 {%0,%1},[%2];" : "=r"(x), "=r"(y) : "r"(a));
}
__device__ __forceinline__ void sts64(u32 a, u32 x, u32 y) {
    asm volatile("st.shared.v2.u32 [%0],{%1,%2};" :: "r"(a), "r"(x), "r"(y));
}
__device__ __forceinline__ void cpasync16(u32 s, const void* g) {
    asm volatile("cp.async.ca.shared.global [%0],[%1],16;" :: "r"(s), "l"(g));
}
__device__ __forceinline__ void cpcommit() { asm volatile("cp.async.commit_group;"); }
__device__ __forceinline__ void cpwaitall() { asm volatile("cp.async.wait_group 0;"); }
__device__ __forceinline__ void named_bar(int id) {
    asm volatile("bar.sync %0, 128;" :: "r"(id) : "memory");
}
// single-MUFU tanh (sm_75+ tanh.approx)
__device__ __forceinline__ float tanha(float x) {
    float y; asm("tanh.approx.f32 %0, %1;" : "=f"(y) : "f"(x)); return y;
}
// sigmoid(x) = 0.5 + 0.5*tanh(x/2)  -> 1 MUFU + 2 FMA
__device__ __forceinline__ float sigmf(float x) {
    return fmaf(tanha(0.5f * x), 0.5f, 0.5f);
}
__device__ __forceinline__ float tanhfast(float x) { return tanha(x); }

// SMEM layout (bytes), 112-row CTA:
//   fp16 states S0,S1,S2 (h0,h1,h2) at s*14336          = 43008
//   output partials at SO_P (7mt x 4q x 16 x 2 f32)     = 3584
//   weights (single resident copy) at SO_W              = 147456
#define SO_P   43008
#define SO_W   46592
#define SMEMSZ (SO_W + 147456)   /* 194048 */

extern "C" __global__ void __launch_bounds__(NTH, 1)
gru_mma_kernel(const float* __restrict__ enc,
               const float* __restrict__ out_w,
               const float* __restrict__ out_b,
               float* __restrict__ out)
{
    extern __shared__ char smc[];
    const u32 sb   = smem_u32(smc);
    const int tid  = threadIdx.x;
    const int lane = tid & 31;
    const int warp = tid >> 5;            // 28 warps
    const int mt   = warp >> 2;           // 7 mtiles x 16 rows
    const int q    = warp & 3;            // column quarter (16 cols of 64)
    const int g    = lane >> 2;
    const int tg   = lane & 3;
    const int row0 = blockIdx.x * MTILE;
    const int barid = 1 + mt;             // per-mt named barrier (128 threads)

    // x-source / h-source state index per layer (x of layer0 = h2 = S[2])
    const int xs[3] = {2, 0, 1};
    const int hs[3] = {0, 1, 2};

    // ---- load ALL weights into SMEM once (resident for the whole run) ----
    for (int o = tid * 16; o < 147456; o += NTH * 16)
        cpasync16(sb + SO_W + o, (const char*)g_wh + o);
    cpcommit();

    // ---- init fp16 states from enc (guarded rows) ----
    for (int i = tid; i < MTILE * 32; i += NTH) {
        int m = i >> 5, kp = i & 31;
        int k = kp * 2;
        int rr = row0 + m; if (rr > 16383) rr = 16383;
        float v0 = enc[(size_t)rr * 64 + k];
        float v1 = enc[(size_t)rr * 64 + k + 1];
        u32 h16 = packh(v0, v1);
        int kt = k >> 4, kin = k & 15;
        int gg = m & 15;
        int reg = ((kin >= 8) ? 2 : 0) + ((gg >= 8) ? 1 : 0);
        int ln = (gg & 7) * 4 + ((kin & 7) >> 1);
        u32 off = (u32)((m >> 4) * 2048 + kt * 512 + ln * 16 + reg * 4);
        #pragma unroll
        for (int s = 0; s < 3; s++)
            *(u32*)(smc + s * 14336 + off) = h16;
    }
    cpwaitall();
    __syncthreads();   // the ONLY CTA-wide barrier; hot loop uses per-mt bars

    const u32 aoff = (u32)(mt * 2048 + lane * 16);
    float* sp = (float*)(smc + SO_P);

    #pragma unroll 1
    for (int t = 0; t < TSTEPS; t++) {

        #pragma unroll 1
        for (int l = 0; l < 3; l++) {

            float aR[2][4], aZ[2][4], aN[2][4], aM[2][4];
            #pragma unroll
            for (int j = 0; j < 2; j++)
                #pragma unroll
                for (int e = 0; e < 4; e++) { aR[j][e]=0.f; aZ[j][e]=0.f; aN[j][e]=0.f; aM[j][e]=0.f; }

            {
                #pragma unroll
                for (int side = 0; side < 2; side++) {    // 0 = x-side, 1 = h-side
                    const int stA = (side == 0) ? xs[l] : hs[l];
                    const u32 abase = sb + (u32)(stA * 14336) + aoff;
                    const u32 wside = sb + SO_W + (u32)(l * 49152 + side * 24576);
                    #pragma unroll 1
                    for (int kt = 0; kt < 4; kt++) {
                        u32 ah[4];
                        lds128(ah, abase + (u32)(kt * 512));
                        #pragma unroll
                        for (int gate = 0; gate < 3; gate++) {
                            float (*acc)[4] = (gate == 0) ? aR :
                                              (gate == 1) ? aZ :
                                              ((side == 0) ? aN : aM);
                            u32 b4[4];
                            lds128(b4, wside + (u32)(((kt * 12 + gate * 4 + q) * 32 + lane) * 16));
                            mma16816h(acc[0], ah, b4[0], b4[1]);
                            mma16816h(acc[1], ah, b4[2], b4[3]);
                        }
                    }
                }
            }
            // q-peers' A-loads of h_l must finish before epilogue rewrites it
            named_bar(barid);

            // ---- layer epilogue (h_old from fp16 state) ----
            const float* gb = g_bias + l * 256;
            const u32 hbase16 = sb + (u32)(hs[l] * 14336) + aoff;
            float oA0 = 0.f, oA1 = 0.f, oB0 = 0.f, oB1 = 0.f;
            #pragma unroll
            for (int j = 0; j < 2; j++) {
                int ntc = q * 2 + j;
                int c0 = ntc * 8 + 2 * tg;
                float br0 = __ldg(gb + c0),        br1 = __ldg(gb + c0 + 1);
                float bz0 = __ldg(gb + 64 + c0),   bz1 = __ldg(gb + 64 + c0 + 1);
                float bn0 = __ldg(gb + 128 + c0),  bn1 = __ldg(gb + 128 + c0 + 1);
                float bm0 = __ldg(gb + 192 + c0),  bm1 = __ldg(gb + 192 + c0 + 1);
                u32 ad16 = hbase16 + (u32)((ntc >> 1) * 512 + (ntc & 1) * 8);
                u32 hh0, hh1;
                lds64(hh0, hh1, ad16);
                float2 hoA = __half22float2(*reinterpret_cast<__half2*>(&hh0));
                float2 hoB = __half22float2(*reinterpret_cast<__half2*>(&hh1));

                float r, z, n;
                r = sigmf(aR[j][0] + br0); z = sigmf(aZ[j][0] + bz0);
                n = tanhfast(aN[j][0] + bn0 + r * (aM[j][0] + bm0));
                float h00 = n + z * (hoA.x - n);
                r = sigmf(aR[j][1] + br1); z = sigmf(aZ[j][1] + bz1);
                n = tanhfast(aN[j][1] + bn1 + r * (aM[j][1] + bm1));
                float h01 = n + z * (hoA.y - n);
                r = sigmf(aR[j][2] + br0); z = sigmf(aZ[j][2] + bz0);
                n = tanhfast(aN[j][2] + bn0 + r * (aM[j][2] + bm0));
                float h10 = n + z * (hoB.x - n);
                r = sigmf(aR[j][3] + br1); z = sigmf(aZ[j][3] + bz1);
                n = tanhfast(aN[j][3] + bn1 + r * (aM[j][3] + bm1));
                float h11 = n + z * (hoB.y - n);

                sts64(ad16, packh(h00, h01), packh(h10, h11));

                if (l == 2) {
                    float w00 = __ldg(out_w + c0),      w01 = __ldg(out_w + c0 + 1);
                    float w10 = __ldg(out_w + 64 + c0), w11 = __ldg(out_w + 64 + c0 + 1);
                    oA0 += h00 * w00 + h01 * w01;
                    oA1 += h00 * w10 + h01 * w11;
                    oB0 += h10 * w00 + h11 * w01;
                    oB1 += h10 * w10 + h11 * w11;
                }
            }
            if (l == 2) {
                #pragma unroll
                for (int m = 1; m <= 2; m <<= 1) {
                    oA0 += __shfl_xor_sync(0xffffffffu, oA0, m);
                    oA1 += __shfl_xor_sync(0xffffffffu, oA1, m);
                    oB0 += __shfl_xor_sync(0xffffffffu, oB0, m);
                    oB1 += __shfl_xor_sync(0xffffffffu, oB1, m);
                }
                if (tg == 0) {
                    int base = ((mt * 4 + q) * 16 + g) * 2;
                    sp[base]     = oA0;
                    sp[base + 1] = oA1;
                    int base2 = ((mt * 4 + q) * 16 + g + 8) * 2;
                    sp[base2]     = oB0;
                    sp[base2 + 1] = oB1;
                }
            }

            // epilogue state writes (and partials) visible to mt peers
            named_bar(barid);

            if (l == 2 && q == 0) {
                int row = lane >> 1, j = lane & 1;
                float v = sp[((mt * 4 + 0) * 16 + row) * 2 + j] +
                          sp[((mt * 4 + 1) * 16 + row) * 2 + j] +
                          sp[((mt * 4 + 2) * 16 + row) * 2 + j] +
                          sp[((mt * 4 + 3) * 16 + row) * 2 + j] + __ldg(out_b + j);
                int grow = row0 + mt * 16 + row;
                if (grow < 16384)
                    out[(size_t)grow * (TSTEPS * 2) + t * 2 + j] = v;
            }
        }
    }
}

extern "C" void kernel_launch(void* const* d_in, const int* in_sizes, int n_in,
                              void* d_out, int out_size)
{
    const float* enc   = (const float*)d_in[0];
    const float* emb_w = (const float*)d_in[1];
    const float* emb_b = (const float*)d_in[2];
    const float* w_ih  = (const float*)d_in[3];
    const float* w_hh  = (const float*)d_in[4];
    const float* b_ih  = (const float*)d_in[5];
    const float* b_hh  = (const float*)d_in[6];
    const float* out_w = (const float*)d_in[7];
    const float* out_b = (const float*)d_in[8];

    cudaFuncSetAttribute(gru_mma_kernel,
                         cudaFuncAttributeMaxDynamicSharedMemorySize, SMEMSZ);

    prep_kernel<<<96, 256>>>(emb_w, emb_b, w_ih, w_hh, b_ih, b_hh);
    gru_mma_kernel<<<152, NTH, SMEMSZ>>>(enc, out_w, out_b, (float*)d_out);
}

// round 17
// speedup vs baseline: 1.2031x; 1.0322x over previous
#include <cuda_runtime.h>
#include <cuda_fp16.h>

typedef unsigned long long u64;
typedef unsigned int u32;

#define TSTEPS 128
#define NTH    896
#define MTILE  112

// =============== prepped weights (global scratch), fp16 ===============
// g_wh layout [l][side][kt(4)][gate(3)][q(4)][lane(32)][j(2)][reg(2)] u32
//   side0 = x-side weights (layer0: fused Wi0@We), side1 = w_hh
__device__ __align__(16) u32 g_wh[3 * 2 * 4 * 3 * 4 * 32 * 2 * 2];   // 36864 u32 = 147456 B
// per-thread packed biases: [l][q][j][tg][8] = {br0,br1,bz0,bz1,bn0,bn1,bm0,bm1}
__device__ __align__(16) float g_biasT[3 * 4 * 2 * 4 * 8];           // 768 floats
// per-thread packed out weights: [q][j][tg][4] = {w00,w01,w10,w11}
__device__ __align__(16) float g_outwT[4 * 2 * 4 * 4];               // 128 floats

__device__ __forceinline__ u32 packh(float a, float b) {
    __half2 h2 = __floats2half2_rn(a, b);
    return *reinterpret_cast<u32*>(&h2);
}

__global__ void prep_kernel(const float* __restrict__ emb_w,
                            const float* __restrict__ emb_b,
                            const float* __restrict__ w_ih,
                            const float* __restrict__ w_hh,
                            const float* __restrict__ b_ih,
                            const float* __restrict__ b_hh,
                            const float* __restrict__ out_w)
{
    int i0 = blockIdx.x * blockDim.x + threadIdx.x;
    int st = gridDim.x * blockDim.x;
    for (int i = i0; i < 36864; i += st) {
        int reg  = i & 1;
        int j    = (i >> 1) & 1;
        int lane = (i >> 2) & 31;
        int qq   = (i >> 7) & 3;
        int gate = (i >> 9) % 3;
        int kt   = (i / 1536) % 4;
        int side = (i / 6144) % 2;
        int l    = i / 12288;
        int g = lane >> 2, tg = lane & 3;
        int n = (gate * 8 + qq * 2 + j) * 8 + g;        // column 0..191
        int k0 = kt * 16 + tg * 2 + reg * 8;
        float w0, w1;
        if (side == 1) {
            w0 = w_hh[(l * 192 + n) * 64 + k0];
            w1 = w_hh[(l * 192 + n) * 64 + k0 + 1];
        } else if (l > 0) {
            w0 = w_ih[(l * 192 + n) * 64 + k0];
            w1 = w_ih[(l * 192 + n) * 64 + k0 + 1];
        } else {
            // fused: Wf[n,k] = sum_e Wi0[n,e] * emb_w[e,k]
            float s0 = 0.f, s1 = 0.f;
            for (int e = 0; e < 64; e++) {
                float wi = w_ih[n * 64 + e];
                s0 += wi * emb_w[e * 64 + k0];
                s1 += wi * emb_w[e * 64 + k0 + 1];
            }
            w0 = s0; w1 = s1;
        }
        g_wh[i] = packh(w0, w1);
    }
    // packed per-thread biases
    for (int i = i0; i < 768; i += st) {
        int e  = i & 7;
        int tg = (i >> 3) & 3;
        int j  = (i >> 5) & 1;
        int qq = (i >> 6) & 3;
        int l  = i >> 8;
        int c = (qq * 2 + j) * 8 + 2 * tg + (e & 1);
        int gate = e >> 1;                 // 0=r 1=z 2=n(i) 3=n(h)
        float v;
        if (gate == 0)      v = b_ih[l * 192 + c]       + b_hh[l * 192 + c];
        else if (gate == 1) v = b_ih[l * 192 + 64 + c]  + b_hh[l * 192 + 64 + c];
        else if (gate == 2) v = b_ih[l * 192 + 128 + c];
        else                v = b_hh[l * 192 + 128 + c];
        if (l == 0 && gate < 3) {
            float bf = 0.f;
            for (int e2 = 0; e2 < 64; e2++)
                bf += emb_b[e2] * w_ih[(gate * 64 + c) * 64 + e2];
            v += bf;
        }
        g_biasT[i] = v;
    }
    // packed out weights
    for (int i = i0; i < 128; i += st) {
        int e  = i & 3;
        int tg = (i >> 2) & 3;
        int j  = (i >> 4) & 1;
        int qq = (i >> 5) & 3;
        int c0 = (qq * 2 + j) * 8 + 2 * tg;
        float v = (e == 0) ? out_w[c0] :
                  (e == 1) ? out_w[c0 + 1] :
                  (e == 2) ? out_w[64 + c0] : out_w[64 + c0 + 1];
        g_outwT[i] = v;
    }
}

// =============== device helpers ===============
__device__ __forceinline__ u32 smem_u32(const void* p) {
    u32 a;
    asm("{ .reg .u64 t; cvta.to.shared.u64 t, %1; cvt.u32.u64 %0, t; }" : "=r"(a) : "l"(p));
    return a;
}
__device__ __forceinline__ void mma16816h(float* d, const u32* a, u32 b0, u32 b1) {
    asm volatile(
        "mma.sync.aligned.m16n8k16.row.col.f32.f16.f16.f32 "
        "{%0,%1,%2,%3},{%4,%5,%6,%7},{%8,%9},{%0,%1,%2,%3};"
        : "+f"(d[0]), "+f"(d[1]), "+f"(d[2]), "+f"(d[3])
        : "r"(a[0]), "r"(a[1]), "r"(a[2]), "r"(a[3]), "r"(b0), "r"(b1));
}
__device__ __forceinline__ void lds128(u32* r, u32 a) {
    asm volatile("ld.shared.v4.u32 {%0,%1,%2,%3},[%4];"
                 : "=r"(r[0]), "=r"(r[1]), "=r"(r[2]), "=r"(r[3]) : "r"(a));
}
__device__ __forceinline__ void sts64(u32 a, u32 x, u32 y) {
    asm volatile("st.shared.v2.u32 [%0],{%1,%2};" :: "r"(a), "r"(x), "r"(y));
}
__device__ __forceinline__ void cpasync16(u32 s, const void* g) {
    asm volatile("cp.async.ca.shared.global [%0],[%1],16;" :: "r"(s), "l"(g));
}
__device__ __forceinline__ void cpcommit() { asm volatile("cp.async.commit_group;"); }
__device__ __forceinline__ void cpwaitall() { asm volatile("cp.async.wait_group 0;"); }
__device__ __forceinline__ void named_bar(int id) {
    asm volatile("bar.sync %0, 128;" :: "r"(id) : "memory");
}
// single-MUFU tanh (sm_75+ tanh.approx)
__device__ __forceinline__ float tanha(float x) {
    float y; asm("tanh.approx.f32 %0, %1;" : "=f"(y) : "f"(x)); return y;
}
// sigmoid(x) = 0.5 + 0.5*tanh(x/2)  -> 1 MUFU + 2 FMA
__device__ __forceinline__ float sigmf(float x) {
    return fmaf(tanha(0.5f * x), 0.5f, 0.5f);
}

// SMEM layout (bytes), 112-row CTA:
//   fp16 states S0,S1,S2 (h0,h1,h2) at s*14336          = 43008
//   output partials at SO_P (7mt x 4q x 16 x 2 f32)     = 3584
//   weights (single resident copy) at SO_W              = 147456
#define SO_P   43008
#define SO_W   46592
#define SMEMSZ (SO_W + 147456)   /* 194048 */

extern "C" __global__ void __launch_bounds__(NTH, 1)
gru_mma_kernel(const float* __restrict__ enc,
               const float* __restrict__ out_b,
               float* __restrict__ out)
{
    extern __shared__ char smc[];
    const u32 sb   = smem_u32(smc);
    const int tid  = threadIdx.x;
    const int lane = tid & 31;
    const int warp = tid >> 5;            // 28 warps
    const int mt   = warp >> 2;           // 7 mtiles x 16 rows
    const int q    = warp & 3;            // column quarter (16 cols of 64)
    const int g    = lane >> 2;
    const int tg   = lane & 3;
    const int row0 = blockIdx.x * MTILE;
    const int barid = 1 + mt;             // per-mt named barrier (128 threads)

    // x-source / h-source state index per layer (x of layer0 = h2 = S[2])
    const int xs[3] = {2, 0, 1};
    const int hs[3] = {0, 1, 2};

    // ---- load ALL weights into SMEM once (resident for the whole run) ----
    for (int o = tid * 16; o < 147456; o += NTH * 16)
        cpasync16(sb + SO_W + o, (const char*)g_wh + o);
    cpcommit();

    // ---- init fp16 states from enc (guarded rows) ----
    for (int i = tid; i < MTILE * 32; i += NTH) {
        int m = i >> 5, kp = i & 31;
        int k = kp * 2;
        int rr = row0 + m; if (rr > 16383) rr = 16383;
        float v0 = enc[(size_t)rr * 64 + k];
        float v1 = enc[(size_t)rr * 64 + k + 1];
        u32 h16 = packh(v0, v1);
        int kt = k >> 4, kin = k & 15;
        int gg = m & 15;
        int reg = ((kin >= 8) ? 2 : 0) + ((gg >= 8) ? 1 : 0);
        int ln = (gg & 7) * 4 + ((kin & 7) >> 1);
        u32 off = (u32)((m >> 4) * 2048 + kt * 512 + ln * 16 + reg * 4);
        #pragma unroll
        for (int s = 0; s < 3; s++)
            *(u32*)(smc + s * 14336 + off) = h16;
    }
    cpwaitall();
    __syncthreads();   // the ONLY CTA-wide barrier; hot loop uses per-mt bars

    const u32 aoff = (u32)(mt * 2048 + lane * 16);
    float* sp = (float*)(smc + SO_P);

    #pragma unroll 1
    for (int t = 0; t < TSTEPS; t++) {

        #pragma unroll 1
        for (int l = 0; l < 3; l++) {

            float aR[2][4], aZ[2][4], aN[2][4], aM[2][4];
            #pragma unroll
            for (int j = 0; j < 2; j++)
                #pragma unroll
                for (int e = 0; e < 4; e++) { aR[j][e]=0.f; aZ[j][e]=0.f; aN[j][e]=0.f; aM[j][e]=0.f; }

            // ---- x-side pass ----
            {
                const u32 abase = sb + (u32)(xs[l] * 14336) + aoff;
                const u32 wside = sb + SO_W + (u32)(l * 49152);
                #pragma unroll 1
                for (int kt = 0; kt < 4; kt++) {
                    u32 ah[4];
                    lds128(ah, abase + (u32)(kt * 512));
                    #pragma unroll
                    for (int gate = 0; gate < 3; gate++) {
                        float (*acc)[4] = (gate == 0) ? aR : (gate == 1) ? aZ : aN;
                        u32 b4[4];
                        lds128(b4, wside + (u32)(((kt * 12 + gate * 4 + q) * 32 + lane) * 16));
                        mma16816h(acc[0], ah, b4[0], b4[1]);
                        mma16816h(acc[1], ah, b4[2], b4[3]);
                    }
                }
            }
            // ---- h-side pass, kt rotated to END at kt==q so ahh == h_old frag ----
            u32 ahh[4];
            {
                const u32 abase = sb + (u32)(hs[l] * 14336) + aoff;
                const u32 wside = sb + SO_W + (u32)(l * 49152 + 24576);
                #pragma unroll 1
                for (int kk = 0; kk < 4; kk++) {
                    int kt = (q + 1 + kk) & 3;
                    lds128(ahh, abase + (u32)(kt * 512));
                    #pragma unroll
                    for (int gate = 0; gate < 3; gate++) {
                        float (*acc)[4] = (gate == 0) ? aR : (gate == 1) ? aZ : aM;
                        u32 b4[4];
                        lds128(b4, wside + (u32)(((kt * 12 + gate * 4 + q) * 32 + lane) * 16));
                        mma16816h(acc[0], ahh, b4[0], b4[1]);
                        mma16816h(acc[1], ahh, b4[2], b4[3]);
                    }
                }
            }
            // q-peers' A-loads of h_l must finish before epilogue rewrites it
            named_bar(barid);

            // ---- layer epilogue (h_old from live ahh regs, packed biases) ----
            const float* gbT = g_biasT + (l * 4 + q) * 64 + tg * 8;
            const u32 hbase16 = sb + (u32)(hs[l] * 14336) + aoff;
            float oA0 = 0.f, oA1 = 0.f, oB0 = 0.f, oB1 = 0.f;
            #pragma unroll
            for (int j = 0; j < 2; j++) {
                const float* bp = gbT + j * 32;
                float4 bA = *(const float4*)bp;        // br0,br1,bz0,bz1
                float4 bB = *(const float4*)(bp + 4);  // bn0,bn1,bm0,bm1
                u32 ha = ahh[j * 2], hb = ahh[j * 2 + 1];
                float2 hoA = __half22float2(*reinterpret_cast<__half2*>(&ha));
                float2 hoB = __half22float2(*reinterpret_cast<__half2*>(&hb));

                float r, z, n;
                r = sigmf(aR[j][0] + bA.x); z = sigmf(aZ[j][0] + bA.z);
                n = tanha(aN[j][0] + bB.x + r * (aM[j][0] + bB.z));
                float h00 = n + z * (hoA.x - n);
                r = sigmf(aR[j][1] + bA.y); z = sigmf(aZ[j][1] + bA.w);
                n = tanha(aN[j][1] + bB.y + r * (aM[j][1] + bB.w));
                float h01 = n + z * (hoA.y - n);
                r = sigmf(aR[j][2] + bA.x); z = sigmf(aZ[j][2] + bA.z);
                n = tanha(aN[j][2] + bB.x + r * (aM[j][2] + bB.z));
                float h10 = n + z * (hoB.x - n);
                r = sigmf(aR[j][3] + bA.y); z = sigmf(aZ[j][3] + bA.w);
                n = tanha(aN[j][3] + bB.y + r * (aM[j][3] + bB.w));
                float h11 = n + z * (hoB.y - n);

                int ntc = q * 2 + j;
                u32 ad16 = hbase16 + (u32)((ntc >> 1) * 512 + (ntc & 1) * 8);
                sts64(ad16, packh(h00, h01), packh(h10, h11));

                if (l == 2) {
                    float4 wv = *(const float4*)(g_outwT + ((q * 2 + j) * 4 + tg) * 4);
                    oA0 += h00 * wv.x + h01 * wv.y;
                    oA1 += h00 * wv.z + h01 * wv.w;
                    oB0 += h10 * wv.x + h11 * wv.y;
                    oB1 += h10 * wv.z + h11 * wv.w;
                }
            }
            if (l == 2) {
                #pragma unroll
                for (int m = 1; m <= 2; m <<= 1) {
                    oA0 += __shfl_xor_sync(0xffffffffu, oA0, m);
                    oA1 += __shfl_xor_sync(0xffffffffu, oA1, m);
                    oB0 += __shfl_xor_sync(0xffffffffu, oB0, m);
                    oB1 += __shfl_xor_sync(0xffffffffu, oB1, m);
                }
                if (tg == 0) {
                    int base = ((mt * 4 + q) * 16 + g) * 2;
                    sp[base]     = oA0;
                    sp[base + 1] = oA1;
                    int base2 = ((mt * 4 + q) * 16 + g + 8) * 2;
                    sp[base2]     = oB0;
                    sp[base2 + 1] = oB1;
                }
            }

            // epilogue state writes (and partials) visible to mt peers
            named_bar(barid);

            if (l == 2 && q == 0) {
                int row = lane >> 1, j = lane & 1;
                float v = sp[((mt * 4 + 0) * 16 + row) * 2 + j] +
                          sp[((mt * 4 + 1) * 16 + row) * 2 + j] +
                          sp[((mt * 4 + 2) * 16 + row) * 2 + j] +
                          sp[((mt * 4 + 3) * 16 + row) * 2 + j] + __ldg(out_b + j);
                int grow = row0 + mt * 16 + row;
                if (grow < 16384)
                    out[(size_t)grow * (TSTEPS * 2) + t * 2 + j] = v;
            }
        }
    }
}

extern "C" void kernel_launch(void* const* d_in, const int* in_sizes, int n_in,
                              void* d_out, int out_size)
{
    const float* enc   = (const float*)d_in[0];
    const float* emb_w = (const float*)d_in[1];
    const float* emb_b = (const float*)d_in[2];
    const float* w_ih  = (const float*)d_in[3];
    const float* w_hh  = (const float*)d_in[4];
    const float* b_ih  = (const float*)d_in[5];
    const float* b_hh  = (const float*)d_in[6];
    const float* out_w = (const float*)d_in[7];
    const float* out_b = (const float*)d_in[8];

    cudaFuncSetAttribute(gru_mma_kernel,
                         cudaFuncAttributeMaxDynamicSharedMemorySize, SMEMSZ);

    prep_kernel<<<96, 256>>>(emb_w, emb_b, w_ih, w_hh, b_ih, b_hh, out_w);
    gru_mma_kernel<<<152, NTH, SMEMSZ>>>(enc, out_b, (float*)d_out);
}